// round 8
// baseline (speedup 1.0000x reference)
#include <cuda_runtime.h>
#include <cstdint>

// ---------------------------------------------------------------------------
// GIN graph network. N=100000 nodes, E=1.25M edges, D=64, L=4, B=2048.
// GEMMs via mma.sync m16n8k8 tf32, 3-pass hi/lo split (== fp32 accuracy).
// BN stats fused into GEMM epilogues.
// ---------------------------------------------------------------------------

#define MAXN 100000
#define MAXE 1250000
#define MAXB 2048

__device__ __align__(16) float g_h[(size_t)MAXN * 64];
__device__ __align__(16) float g_agg[(size_t)MAXN * 64];   // also reused as y2
__device__ __align__(16) float g_y1[(size_t)MAXN * 128];
__device__ __align__(16) float g_stats[384];  // [0:128) sum1 [128:256) sq1 [256:320) sum2 [320:384) sq2
__device__ __align__(16) float g_bn1[256];    // scale1[128], shift1[128]
__device__ __align__(16) float g_bn2[128];    // scale2[64], shift2[64]
__device__ float g_cnt[MAXB];

__device__ __forceinline__ void red_add_v4(float* addr, float4 v) {
    asm volatile("red.global.add.v4.f32 [%0], {%1,%2,%3,%4};"
                 :: "l"(addr), "f"(v.x), "f"(v.y), "f"(v.z), "f"(v.w)
                 : "memory");
}

// tf32 split: hi = fp32 with low 13 mantissa bits cleared (exact tf32), lo = x - hi
__device__ __forceinline__ float tf32_hi(float x) {
    return __uint_as_float(__float_as_uint(x) & 0xFFFFE000u);
}

// mma.sync m16n8k8 tf32: D += A*B (C==D accumulate in-place)
__device__ __forceinline__ void mma8(float* d, uint4 a, uint2 b) {
    asm volatile(
        "mma.sync.aligned.m16n8k8.row.col.f32.tf32.tf32.f32 "
        "{%0,%1,%2,%3}, {%4,%5,%6,%7}, {%8,%9}, {%0,%1,%2,%3};"
        : "+f"(d[0]), "+f"(d[1]), "+f"(d[2]), "+f"(d[3])
        : "r"(a.x), "r"(a.y), "r"(a.z), "r"(a.w), "r"(b.x), "r"(b.y));
}

// ---------------------------------------------------------------------------
// Atom encoder
// ---------------------------------------------------------------------------
__global__ __launch_bounds__(256) void atom_kernel(
    const float* __restrict__ atom_emb, const int* __restrict__ x_feat, int n)
{
    int wi = blockIdx.x * 256 + threadIdx.x;
    int nid = wi >> 4;
    if (nid >= n) return;
    int c = wi & 15;
    const float4* ae = (const float4*)atom_emb;  // [9,128,16] float4
    float4 acc = make_float4(0.f, 0.f, 0.f, 0.f);
#pragma unroll
    for (int f = 0; f < 9; f++) {
        int idx = __ldg(&x_feat[nid * 9 + f]);
        float4 v = ae[(f * 128 + idx) * 16 + c];
        acc.x += v.x; acc.y += v.y; acc.z += v.z; acc.w += v.w;
    }
    ((float4*)g_h)[(size_t)nid * 16 + c] = acc;
}

// ---------------------------------------------------------------------------
// Clears
// ---------------------------------------------------------------------------
__global__ __launch_bounds__(256) void clear_agg_kernel(int count4)
{
    int i = blockIdx.x * 256 + threadIdx.x;
    if (i < count4) ((float4*)g_agg)[i] = make_float4(0.f, 0.f, 0.f, 0.f);
}
__global__ void clear_stats_kernel()
{
    int i = threadIdx.x;
    if (i < 384) g_stats[i] = 0.f;
}
__global__ __launch_bounds__(256) void clear_pool_kernel(float* __restrict__ gout, int b)
{
    int i = blockIdx.x * 256 + threadIdx.x;
    if (i < b * 64) gout[i] = 0.f;
    if (i < b) g_cnt[i] = 0.f;
}

// ---------------------------------------------------------------------------
// Edge kernel (unchanged — known good)
// ---------------------------------------------------------------------------
__global__ __launch_bounds__(256) void edge_kernel(
    const float* __restrict__ bond_emb_l, const int* __restrict__ edge_index,
    const int* __restrict__ edge_attr, int e)
{
    __shared__ float bemb[1536];
    for (int i = threadIdx.x; i < 1536; i += 256) bemb[i] = bond_emb_l[i];
    __syncthreads();

    long long wi = (long long)blockIdx.x * 256 + threadIdx.x;
    int eidx = (int)(wi >> 4);
    int c = threadIdx.x & 15;
    bool valid = eidx < e;

    int src = 0, dst = 0, a0 = 0, a1 = 0, a2 = 0;
    if (valid && c == 0) {
        src = edge_index[eidx];
        dst = edge_index[e + eidx];
        a0 = edge_attr[3 * eidx + 0];
        a1 = edge_attr[3 * eidx + 1];
        a2 = edge_attr[3 * eidx + 2];
    }
    int lane = threadIdx.x & 31;
    int leader = lane & 16;
    src = __shfl_sync(0xffffffffu, src, leader);
    dst = __shfl_sync(0xffffffffu, dst, leader);
    a0  = __shfl_sync(0xffffffffu, a0, leader);
    a1  = __shfl_sync(0xffffffffu, a1, leader);
    a2  = __shfl_sync(0xffffffffu, a2, leader);
    if (!valid) return;

    const float4* b4 = (const float4*)bemb;
    float4 e0 = b4[a0 * 16 + c];
    float4 e1 = b4[(8 + a1) * 16 + c];
    float4 e2 = b4[(16 + a2) * 16 + c];
    float4 hv = ((const float4*)g_h)[(size_t)src * 16 + c];
    float4 m;
    m.x = fmaxf(hv.x + e0.x + e1.x + e2.x, 0.f);
    m.y = fmaxf(hv.y + e0.y + e1.y + e2.y, 0.f);
    m.z = fmaxf(hv.z + e0.z + e1.z + e2.z, 0.f);
    m.w = fmaxf(hv.w + e0.w + e1.w + e2.w, 0.f);
    red_add_v4(g_agg + (size_t)dst * 64 + c * 4, m);
}

// ---------------------------------------------------------------------------
// GEMM1 (mma.sync tf32): z = (1+eps)*h + agg [128 x 64] -> y1 = z@W1 + b1
// [128 x 128]. Fragments pre-staged in smem in mma layout. Stats fused.
//
// Fragment layouts (m16n8k8):
//   A frag idx: ((ks*RA + ra)*32 + lane)*4 + reg,  reg = ((c8>>2)<<1)|(r16>>3)
//               lane = (r16&7)*4 + (c8&3)
//   B frag idx: ((ks*CA + ca)*32 + lane)*2 + reg,  reg = (k8)>>2
//               lane = (n8)*4 + (k&3)
// smem bytes: A_HI 0 (32K), A_LO 32768, B_HI 65536 (32K), B_LO 98304,
//             STAT 131072 (1K). total 132096.
// ---------------------------------------------------------------------------
#define G1_SMEM 132096

__global__ __launch_bounds__(256, 1) void gemm1_mma_kernel(
    const float* __restrict__ W1, const float* __restrict__ b1,
    const float* __restrict__ epsp, int n)
{
    extern __shared__ char smem[];
    float* Ah = (float*)smem;
    float* Al = (float*)(smem + 32768);
    float* Bh = (float*)(smem + 65536);
    float* Bl = (float*)(smem + 98304);
    float* sstat = (float*)(smem + 131072);   // 128 sums + 128 sq

    int tid = threadIdx.x;
    int wid = tid >> 5;
    int lane = tid & 31;

    for (int i = tid; i < 256; i += 256) sstat[i] = 0.f;

    // Stage W1 [64K x 128N] into B fragments (hi/lo).
    for (int i = tid; i < 8192; i += 256) {
        int k = i >> 7, nn = i & 127;
        float w = __ldg(&W1[i]);
        float hi = tf32_hi(w);
        int idx = (((k >> 3) * 16 + (nn >> 3)) * 32 + (nn & 7) * 4 + (k & 3)) * 2 + ((k & 7) >> 2);
        Bh[idx] = hi;
        Bl[idx] = w - hi;
    }

    // Stage A = (1+eps)*h + agg into A fragments (hi/lo).
    float epsv = 1.0f + __ldg(epsp);
    int r0 = blockIdx.x * 128;
    for (int i = tid; i < 2048; i += 256) {   // 128 rows * 16 float4
        int rr = i >> 4, cc4 = i & 15;
        int row = r0 + rr;
        float4 z = make_float4(0.f, 0.f, 0.f, 0.f);
        if (row < n) {
            float4 hv = ((const float4*)g_h)[(size_t)row * 16 + cc4];
            float4 av = ((const float4*)g_agg)[(size_t)row * 16 + cc4];
            z.x = fmaf(epsv, hv.x, av.x);
            z.y = fmaf(epsv, hv.y, av.y);
            z.z = fmaf(epsv, hv.z, av.z);
            z.w = fmaf(epsv, hv.w, av.w);
        }
        int ks = cc4 >> 1;
        int ra = rr >> 4;
        int r16 = rr & 15;
        int reg = ((cc4 & 1) << 1) | (r16 >> 3);
        int lbase = (r16 & 7) * 4;
        int idx0 = ((ks * 8 + ra) * 32 + lbase) * 4 + reg;
        float zv[4] = {z.x, z.y, z.z, z.w};
#pragma unroll
        for (int j = 0; j < 4; j++) {
            float hi = tf32_hi(zv[j]);
            Ah[idx0 + 4 * j] = hi;
            Al[idx0 + 4 * j] = zv[j] - hi;
        }
    }
    __syncthreads();

    // Mainloop: warp (wr, wc): rows 32*wr, cols 64*wc.
    int wr = wid >> 1, wc = wid & 1;
    float acc[2][8][4];
#pragma unroll
    for (int ra = 0; ra < 2; ra++)
#pragma unroll
        for (int ca = 0; ca < 8; ca++)
#pragma unroll
            for (int j = 0; j < 4; j++) acc[ra][ca][j] = 0.f;

    const uint4* Ah4 = (const uint4*)Ah;
    const uint4* Al4 = (const uint4*)Al;
    const uint2* Bh2 = (const uint2*)Bh;
    const uint2* Bl2 = (const uint2*)Bl;

#pragma unroll
    for (int ks = 0; ks < 8; ks++) {
        uint4 ah0 = Ah4[(ks * 8 + 2 * wr + 0) * 32 + lane];
        uint4 ah1 = Ah4[(ks * 8 + 2 * wr + 1) * 32 + lane];
        uint4 al0 = Al4[(ks * 8 + 2 * wr + 0) * 32 + lane];
        uint4 al1 = Al4[(ks * 8 + 2 * wr + 1) * 32 + lane];
#pragma unroll
        for (int ca = 0; ca < 8; ca++) {
            uint2 bh = Bh2[(ks * 16 + 8 * wc + ca) * 32 + lane];
            uint2 bl = Bl2[(ks * 16 + 8 * wc + ca) * 32 + lane];
            mma8(acc[0][ca], ah0, bh);
            mma8(acc[0][ca], ah0, bl);
            mma8(acc[0][ca], al0, bh);
            mma8(acc[1][ca], ah1, bh);
            mma8(acc[1][ca], ah1, bl);
            mma8(acc[1][ca], al1, bh);
        }
    }

    // Epilogue: bias, store y1, fused BN stats.
    int g = lane >> 2, t = lane & 3;
    int rowbase = r0 + wr * 32;
#pragma unroll
    for (int ca = 0; ca < 8; ca++) {
        int col = wc * 64 + ca * 8 + t * 2;
        float2 bias = *(const float2*)(b1 + col);
        float se = 0.f, so = 0.f, qe = 0.f, qo = 0.f;
#pragma unroll
        for (int ra = 0; ra < 2; ra++) {
            int rA = rowbase + ra * 16 + g;
            int rB = rA + 8;
            float e0 = acc[ra][ca][0] + bias.x;
            float o0 = acc[ra][ca][1] + bias.y;
            float e1 = acc[ra][ca][2] + bias.x;
            float o1 = acc[ra][ca][3] + bias.y;
            if (rA < n) {
                *(float2*)(g_y1 + (size_t)rA * 128 + col) = make_float2(e0, o0);
                se += e0; so += o0; qe += e0 * e0; qo += o0 * o0;
            }
            if (rB < n) {
                *(float2*)(g_y1 + (size_t)rB * 128 + col) = make_float2(e1, o1);
                se += e1; so += o1; qe += e1 * e1; qo += o1 * o1;
            }
        }
#pragma unroll
        for (int off = 4; off < 32; off <<= 1) {
            se += __shfl_xor_sync(0xffffffffu, se, off);
            so += __shfl_xor_sync(0xffffffffu, so, off);
            qe += __shfl_xor_sync(0xffffffffu, qe, off);
            qo += __shfl_xor_sync(0xffffffffu, qo, off);
        }
        if (lane < 4) {
            int c2 = wc * 64 + ca * 8 + lane * 2;
            atomicAdd(&sstat[c2], se);
            atomicAdd(&sstat[c2 + 1], so);
            atomicAdd(&sstat[128 + c2], qe);
            atomicAdd(&sstat[128 + c2 + 1], qo);
        }
    }
    __syncthreads();
    if (tid < 128) {
        atomicAdd(&g_stats[tid], sstat[tid]);
        atomicAdd(&g_stats[128 + tid], sstat[128 + tid]);
    }
}

// ---------------------------------------------------------------------------
// GEMM2 (mma.sync tf32): t = relu(bn1(y1)) [128 x 128] -> y2 = t@W2 + b2
// [128 x 64] -> g_agg. Stats fused (g_stats[256..384)).
// smem bytes: A_HI 0 (64K), A_LO 65536, B_HI 131072 (32K), B_LO 163840,
//             STAT 196608 (512B). total 197120.
// ---------------------------------------------------------------------------
#define G2_SMEM 197120

__global__ __launch_bounds__(256, 1) void gemm2_mma_kernel(
    const float* __restrict__ W2, const float* __restrict__ b2, int n)
{
    extern __shared__ char smem[];
    float* Ah = (float*)smem;
    float* Al = (float*)(smem + 65536);
    float* Bh = (float*)(smem + 131072);
    float* Bl = (float*)(smem + 163840);
    float* sstat = (float*)(smem + 196608);  // 64 sums + 64 sq

    int tid = threadIdx.x;
    int wid = tid >> 5;
    int lane = tid & 31;

    if (tid < 128) sstat[tid] = 0.f;

    // Stage W2 [128K x 64N] into B fragments (hi/lo).
    for (int i = tid; i < 8192; i += 256) {
        int k = i >> 6, nn = i & 63;
        float w = __ldg(&W2[i]);
        float hi = tf32_hi(w);
        int idx = (((k >> 3) * 8 + (nn >> 3)) * 32 + (nn & 7) * 4 + (k & 3)) * 2 + ((k & 7) >> 2);
        Bh[idx] = hi;
        Bl[idx] = w - hi;
    }

    // Stage A = relu(bn1(y1)) into A fragments (hi/lo).
    int r0 = blockIdx.x * 128;
    for (int i = tid; i < 4096; i += 256) {   // 128 rows * 32 float4
        int rr = i >> 5, cc4 = i & 31;
        int row = r0 + rr;
        float4 z = make_float4(0.f, 0.f, 0.f, 0.f);
        if (row < n) {
            float4 y = ((const float4*)g_y1)[(size_t)row * 32 + cc4];
            float4 sc = ((const float4*)g_bn1)[cc4];
            float4 sh = ((const float4*)g_bn1)[32 + cc4];
            z.x = fmaxf(fmaf(y.x, sc.x, sh.x), 0.f);
            z.y = fmaxf(fmaf(y.y, sc.y, sh.y), 0.f);
            z.z = fmaxf(fmaf(y.z, sc.z, sh.z), 0.f);
            z.w = fmaxf(fmaf(y.w, sc.w, sh.w), 0.f);
        }
        int ks = cc4 >> 1;
        int ra = rr >> 4;
        int r16 = rr & 15;
        int reg = ((cc4 & 1) << 1) | (r16 >> 3);
        int lbase = (r16 & 7) * 4;
        int idx0 = ((ks * 8 + ra) * 32 + lbase) * 4 + reg;
        float zv[4] = {z.x, z.y, z.z, z.w};
#pragma unroll
        for (int j = 0; j < 4; j++) {
            float hi = tf32_hi(zv[j]);
            Ah[idx0 + 4 * j] = hi;
            Al[idx0 + 4 * j] = zv[j] - hi;
        }
    }
    __syncthreads();

    // Mainloop: warp (wr, wc): rows 32*wr, cols 32*wc.
    int wr = wid >> 1, wc = wid & 1;
    float acc[2][4][4];
#pragma unroll
    for (int ra = 0; ra < 2; ra++)
#pragma unroll
        for (int ca = 0; ca < 4; ca++)
#pragma unroll
            for (int j = 0; j < 4; j++) acc[ra][ca][j] = 0.f;

    const uint4* Ah4 = (const uint4*)Ah;
    const uint4* Al4 = (const uint4*)Al;
    const uint2* Bh2 = (const uint2*)Bh;
    const uint2* Bl2 = (const uint2*)Bl;

#pragma unroll
    for (int ks = 0; ks < 16; ks++) {
        uint4 ah0 = Ah4[(ks * 8 + 2 * wr + 0) * 32 + lane];
        uint4 ah1 = Ah4[(ks * 8 + 2 * wr + 1) * 32 + lane];
        uint4 al0 = Al4[(ks * 8 + 2 * wr + 0) * 32 + lane];
        uint4 al1 = Al4[(ks * 8 + 2 * wr + 1) * 32 + lane];
#pragma unroll
        for (int ca = 0; ca < 4; ca++) {
            uint2 bh = Bh2[(ks * 8 + 4 * wc + ca) * 32 + lane];
            uint2 bl = Bl2[(ks * 8 + 4 * wc + ca) * 32 + lane];
            mma8(acc[0][ca], ah0, bh);
            mma8(acc[0][ca], ah0, bl);
            mma8(acc[0][ca], al0, bh);
            mma8(acc[1][ca], ah1, bh);
            mma8(acc[1][ca], ah1, bl);
            mma8(acc[1][ca], al1, bh);
        }
    }

    // Epilogue: bias, store y2 (g_agg), fused BN stats.
    int g = lane >> 2, t = lane & 3;
    int rowbase = r0 + wr * 32;
#pragma unroll
    for (int ca = 0; ca < 4; ca++) {
        int col = wc * 32 + ca * 8 + t * 2;
        float2 bias = *(const float2*)(b2 + col);
        float se = 0.f, so = 0.f, qe = 0.f, qo = 0.f;
#pragma unroll
        for (int ra = 0; ra < 2; ra++) {
            int rA = rowbase + ra * 16 + g;
            int rB = rA + 8;
            float e0 = acc[ra][ca][0] + bias.x;
            float o0 = acc[ra][ca][1] + bias.y;
            float e1 = acc[ra][ca][2] + bias.x;
            float o1 = acc[ra][ca][3] + bias.y;
            if (rA < n) {
                *(float2*)(g_agg + (size_t)rA * 64 + col) = make_float2(e0, o0);
                se += e0; so += o0; qe += e0 * e0; qo += o0 * o0;
            }
            if (rB < n) {
                *(float2*)(g_agg + (size_t)rB * 64 + col) = make_float2(e1, o1);
                se += e1; so += o1; qe += e1 * e1; qo += o1 * o1;
            }
        }
#pragma unroll
        for (int off = 4; off < 32; off <<= 1) {
            se += __shfl_xor_sync(0xffffffffu, se, off);
            so += __shfl_xor_sync(0xffffffffu, so, off);
            qe += __shfl_xor_sync(0xffffffffu, qe, off);
            qo += __shfl_xor_sync(0xffffffffu, qo, off);
        }
        if (lane < 4) {
            int c2 = wc * 32 + ca * 8 + lane * 2;
            atomicAdd(&sstat[c2], se);
            atomicAdd(&sstat[c2 + 1], so);
            atomicAdd(&sstat[64 + c2], qe);
            atomicAdd(&sstat[64 + c2 + 1], qo);
        }
    }
    __syncthreads();
    if (tid < 64) {
        atomicAdd(&g_stats[256 + tid], sstat[tid]);
        atomicAdd(&g_stats[320 + tid], sstat[64 + tid]);
    }
}

// ---------------------------------------------------------------------------
// Finalize BN stats -> scale/shift
// ---------------------------------------------------------------------------
__global__ void finalize_kernel(const float* __restrict__ g, const float* __restrict__ b,
                                int C, int statoff, int which, float nInv)
{
    int t = threadIdx.x;
    if (t >= C) return;
    float mean = g_stats[statoff + t] * nInv;
    float var = g_stats[statoff + C + t] * nInv - mean * mean;
    var = fmaxf(var, 0.f);
    float inv = rsqrtf(var + 1e-5f);
    float scale = __ldg(&g[t]) * inv;
    float shift = __ldg(&b[t]) - mean * scale;
    float* out = which ? g_bn2 : g_bn1;
    out[t] = scale;
    out[C + t] = shift;
}

// ---------------------------------------------------------------------------
// BN2 apply (+relu) -> g_h or d_out node region
// ---------------------------------------------------------------------------
__global__ __launch_bounds__(256) void bn2_apply_kernel(
    float* __restrict__ nodeout, int n, int dorelu, int tofinal)
{
    int i = blockIdx.x * 256 + threadIdx.x;
    if (i >= n * 16) return;
    int c = i & 15;
    float4 y = ((const float4*)g_agg)[i];
    float4 sc = ((const float4*)g_bn2)[c];
    float4 sh = ((const float4*)g_bn2)[16 + c];
    float4 v;
    v.x = fmaf(y.x, sc.x, sh.x);
    v.y = fmaf(y.y, sc.y, sh.y);
    v.z = fmaf(y.z, sc.z, sh.z);
    v.w = fmaf(y.w, sc.w, sh.w);
    if (dorelu) {
        v.x = fmaxf(v.x, 0.f); v.y = fmaxf(v.y, 0.f);
        v.z = fmaxf(v.z, 0.f); v.w = fmaxf(v.w, 0.f);
    }
    float* out = tofinal ? nodeout : g_h;
    ((float4*)out)[i] = v;
}

// ---------------------------------------------------------------------------
// Pooling
// ---------------------------------------------------------------------------
__global__ __launch_bounds__(256) void pool_kernel(
    const float* __restrict__ nodeout, const int* __restrict__ batch,
    float* __restrict__ gout, int n)
{
    int wi = blockIdx.x * 256 + threadIdx.x;
    int nid = wi >> 4;
    if (nid >= n) return;
    int c = wi & 15;
    int b = __ldg(&batch[nid]);
    float4 v = ((const float4*)nodeout)[(size_t)nid * 16 + c];
    red_add_v4(gout + (size_t)b * 64 + c * 4, v);
    if (c == 0) atomicAdd(&g_cnt[b], 1.0f);
}

__global__ __launch_bounds__(256) void divide_kernel(float* __restrict__ gout, int b)
{
    int i = blockIdx.x * 256 + threadIdx.x;
    if (i < b * 64) gout[i] = gout[i] / (g_cnt[i >> 6] + 1e-9f);
}

// ---------------------------------------------------------------------------
// Launch
// ---------------------------------------------------------------------------
extern "C" void kernel_launch(void* const* d_in, const int* in_sizes, int n_in,
                              void* d_out, int out_size)
{
    const float* atom_emb = (const float*)d_in[0];
    const float* bond_emb = (const float*)d_in[1];
    const float* eps      = (const float*)d_in[2];
    const float* W1       = (const float*)d_in[3];
    const float* b1       = (const float*)d_in[4];
    const float* bn1_g    = (const float*)d_in[5];
    const float* bn1_b    = (const float*)d_in[6];
    const float* W2       = (const float*)d_in[7];
    const float* b2       = (const float*)d_in[8];
    const float* bn2_g    = (const float*)d_in[9];
    const float* bn2_b    = (const float*)d_in[10];
    const int* x_feat     = (const int*)d_in[11];
    const int* edge_index = (const int*)d_in[12];
    const int* edge_attr  = (const int*)d_in[13];
    const int* batch      = (const int*)d_in[14];

    int n = in_sizes[11] / 9;
    int e = in_sizes[12] / 2;
    int b = out_size / 64 - n;
    float* nodeout = (float*)d_out;
    float* gout = nodeout + (size_t)n * 64;

    int nodeChunks = n * 16;
    int nodeGrid = (nodeChunks + 255) / 256;
    long long edgeItems = (long long)e * 16;
    int edgeGrid = (int)((edgeItems + 255) / 256);
    int gemmGrid = (n + 127) / 128;
    float nInv = 1.0f / (float)n;

    static int attr_done = 0;
    if (!attr_done) {
        cudaFuncSetAttribute(gemm1_mma_kernel, cudaFuncAttributeMaxDynamicSharedMemorySize, G1_SMEM);
        cudaFuncSetAttribute(gemm2_mma_kernel, cudaFuncAttributeMaxDynamicSharedMemorySize, G2_SMEM);
        attr_done = 1;
    }

    atom_kernel<<<nodeGrid, 256>>>(atom_emb, x_feat, n);

    for (int l = 0; l < 4; l++) {
        clear_agg_kernel<<<nodeGrid, 256>>>(nodeChunks);
        clear_stats_kernel<<<1, 384>>>();
        edge_kernel<<<edgeGrid, 256>>>(bond_emb + l * 1536, edge_index, edge_attr, e);
        gemm1_mma_kernel<<<gemmGrid, 256, G1_SMEM>>>(W1 + l * 64 * 128, b1 + l * 128, eps + l, n);
        finalize_kernel<<<1, 128>>>(bn1_g + l * 128, bn1_b + l * 128, 128, 0, 0, nInv);
        gemm2_mma_kernel<<<gemmGrid, 256, G2_SMEM>>>(W2 + l * 128 * 64, b2 + l * 64, n);
        finalize_kernel<<<1, 64>>>(bn2_g + l * 64, bn2_b + l * 64, 64, 256, 1, nInv);
        bn2_apply_kernel<<<nodeGrid, 256>>>(nodeout, n, (l != 3) ? 1 : 0, (l == 3) ? 1 : 0);
    }

    int poolClear = (b * 64 + 255) / 256;
    clear_pool_kernel<<<poolClear, 256>>>(gout, b);
    pool_kernel<<<nodeGrid, 256>>>(nodeout, batch, gout, n);
    divide_kernel<<<poolClear, 256>>>(gout, b);
}

// round 9
// speedup vs baseline: 1.4132x; 1.4132x over previous
#include <cuda_runtime.h>
#include <cstdint>

// ---------------------------------------------------------------------------
// GIN graph network, fp32. N=100000, E=1.25M, D=64, L=4, B=2048.
// R5 FFMA GEMMs (fused BN stats) + combo-table edge kernel + epilogue fusions.
// ---------------------------------------------------------------------------

#define MAXN 100000
#define MAXE 1250000
#define MAXB 2048

__device__ __align__(16) float g_h[(size_t)MAXN * 64];
__device__ __align__(16) float g_agg[(size_t)MAXN * 64];   // also reused as y2
__device__ __align__(16) float g_y1[(size_t)MAXN * 128];
__device__ __align__(16) float g_stats[384];  // [0:128) sum1 [128:256) sq1 [256:320) sum2 [320:384) sq2
__device__ __align__(16) float g_bn1[256];    // scale1[128], shift1[128]
__device__ __align__(16) float g_bn2[128];    // scale2[64], shift2[64]
__device__ float g_cnt[MAXB];
__device__ int g_combo[MAXE];

__device__ __forceinline__ void red_add_v4(float* addr, float4 v) {
    asm volatile("red.global.add.v4.f32 [%0], {%1,%2,%3,%4};"
                 :: "l"(addr), "f"(v.x), "f"(v.y), "f"(v.z), "f"(v.w)
                 : "memory");
}

// ---------------------------------------------------------------------------
// Atom encoder
// ---------------------------------------------------------------------------
__global__ __launch_bounds__(256) void atom_kernel(
    const float* __restrict__ atom_emb, const int* __restrict__ x_feat, int n)
{
    int wi = blockIdx.x * 256 + threadIdx.x;
    int nid = wi >> 4;
    if (nid >= n) return;
    int c = wi & 15;
    const float4* ae = (const float4*)atom_emb;  // [9,128,16] float4
    float4 acc = make_float4(0.f, 0.f, 0.f, 0.f);
#pragma unroll
    for (int f = 0; f < 9; f++) {
        int idx = __ldg(&x_feat[nid * 9 + f]);
        float4 v = ae[(f * 128 + idx) * 16 + c];
        acc.x += v.x; acc.y += v.y; acc.z += v.z; acc.w += v.w;
    }
    ((float4*)g_h)[(size_t)nid * 16 + c] = acc;
}

// ---------------------------------------------------------------------------
// One-time prep: combo[e] = a0*25 + a1*5 + a2 (edge_attr values are in [0,5))
// ---------------------------------------------------------------------------
__global__ __launch_bounds__(256) void prep_combo_kernel(
    const int* __restrict__ edge_attr, int e)
{
    int i = blockIdx.x * 256 + threadIdx.x;
    if (i >= e) return;
    int a0 = edge_attr[3 * i + 0];
    int a1 = edge_attr[3 * i + 1];
    int a2 = edge_attr[3 * i + 2];
    g_combo[i] = a0 * 25 + a1 * 5 + a2;
}

// ---------------------------------------------------------------------------
// Clears
// ---------------------------------------------------------------------------
__global__ __launch_bounds__(256) void clear_agg_kernel(int count4)
{
    int i = blockIdx.x * 256 + threadIdx.x;
    if (i < count4) ((float4*)g_agg)[i] = make_float4(0.f, 0.f, 0.f, 0.f);
}
__global__ void clear_stats_kernel()
{
    int i = threadIdx.x;
    if (i < 384) g_stats[i] = 0.f;
}
__global__ __launch_bounds__(256) void clear_pool_kernel(float* __restrict__ gout, int b)
{
    int i = blockIdx.x * 256 + threadIdx.x;
    if (i < b * 64) gout[i] = 0.f;
    if (i < b) g_cnt[i] = 0.f;
}

// ---------------------------------------------------------------------------
// Edge kernel: combined 125-combo bond table in smem; grid-stride; per-lane
// broadcast metadata loads (no shuffles). msg = relu(h[src]+table[combo]);
// red-add into agg[dst].
// ---------------------------------------------------------------------------
__global__ __launch_bounds__(256) void edge_kernel(
    const float* __restrict__ bond_emb_l,   // [3,8,64] this layer
    const int* __restrict__ edge_index,     // [2,E]
    int e)
{
    __shared__ __align__(16) float table[125 * 64];   // 31.25 KB

    // Build combined table: table[combo][:] = emb0[a0] + emb1[a1] + emb2[a2]
    const float4* b4 = (const float4*)bond_emb_l;     // [3,8,16] float4
    for (int t = threadIdx.x; t < 2000; t += 256) {   // 125*16 float4
        int combo = t >> 4, c4 = t & 15;
        int a0 = combo / 25;
        int rr = combo - a0 * 25;
        int a1 = rr / 5;
        int a2 = rr - a1 * 5;
        float4 v0 = b4[a0 * 16 + c4];
        float4 v1 = b4[(8 + a1) * 16 + c4];
        float4 v2 = b4[(16 + a2) * 16 + c4];
        float4 s;
        s.x = v0.x + v1.x + v2.x;
        s.y = v0.y + v1.y + v2.y;
        s.z = v0.z + v1.z + v2.z;
        s.w = v0.w + v1.w + v2.w;
        ((float4*)table)[t] = s;
    }
    __syncthreads();

    int c = threadIdx.x & 15;
    long long total = (long long)e * 16;
    long long stride = (long long)gridDim.x * 256;
    for (long long item = (long long)blockIdx.x * 256 + threadIdx.x;
         item < total; item += stride) {
        int eidx = (int)(item >> 4);
        int src = __ldg(&edge_index[eidx]);
        int dst = __ldg(&edge_index[e + eidx]);
        int cb  = __ldg(&g_combo[eidx]);
        float4 ev = ((const float4*)table)[cb * 16 + c];
        float4 hv = ((const float4*)g_h)[(size_t)src * 16 + c];
        float4 m;
        m.x = fmaxf(hv.x + ev.x, 0.f);
        m.y = fmaxf(hv.y + ev.y, 0.f);
        m.z = fmaxf(hv.z + ev.z, 0.f);
        m.w = fmaxf(hv.w + ev.w, 0.f);
        red_add_v4(g_agg + (size_t)dst * 64 + c * 4, m);
    }
}

// ---------------------------------------------------------------------------
// GEMM1 (R5 FFMA): z = (1+eps)*h + agg (64) -> y1 = z@W1 + b1 (128), fused
// BN1 stats. blockDim 128: cg = tid%32 (4 cols), rg = tid/32 (8 rows).
// ---------------------------------------------------------------------------
__global__ __launch_bounds__(128) void gemm1_kernel(
    const float* __restrict__ W1, const float* __restrict__ b1,
    const float* __restrict__ epsp, int n)
{
    __shared__ float Ws[64 * 128];  // 32 KB
    __shared__ float Zs[32 * 64];   // 8 KB (reused for stats reduction)
    int tid = threadIdx.x;

    for (int i = tid; i < 2048; i += 128)
        ((float4*)Ws)[i] = ((const float4*)W1)[i];

    float epsv = 1.0f + __ldg(epsp);
    int r0 = blockIdx.x * 32;
    for (int i = tid; i < 512; i += 128) {   // 32*64/4 float4
        int rr = i >> 4, cc = i & 15;
        int row = r0 + rr;
        float4 z = make_float4(0.f, 0.f, 0.f, 0.f);
        if (row < n) {
            float4 hv = ((const float4*)g_h)[(size_t)row * 16 + cc];
            float4 av = ((const float4*)g_agg)[(size_t)row * 16 + cc];
            z.x = fmaf(epsv, hv.x, av.x);
            z.y = fmaf(epsv, hv.y, av.y);
            z.z = fmaf(epsv, hv.z, av.z);
            z.w = fmaf(epsv, hv.w, av.w);
        }
        ((float4*)Zs)[i] = z;
    }
    __syncthreads();

    int cg = tid & 31;
    int rg = tid >> 5;
    float4 bias = ((const float4*)b1)[cg];
    float4 acc[8];
#pragma unroll
    for (int r = 0; r < 8; r++) acc[r] = bias;

    for (int k = 0; k < 64; k++) {
        float4 w = ((const float4*)Ws)[k * 32 + cg];
#pragma unroll
        for (int r = 0; r < 8; r++) {
            float z = Zs[(rg * 8 + r) * 64 + k];
            acc[r].x = fmaf(z, w.x, acc[r].x);
            acc[r].y = fmaf(z, w.y, acc[r].y);
            acc[r].z = fmaf(z, w.z, acc[r].z);
            acc[r].w = fmaf(z, w.w, acc[r].w);
        }
    }

    float s[4] = {0.f, 0.f, 0.f, 0.f}, sq[4] = {0.f, 0.f, 0.f, 0.f};
#pragma unroll
    for (int r = 0; r < 8; r++) {
        int row = r0 + rg * 8 + r;
        if (row < n) {
            ((float4*)g_y1)[(size_t)row * 32 + cg] = acc[r];
            s[0] += acc[r].x; sq[0] += acc[r].x * acc[r].x;
            s[1] += acc[r].y; sq[1] += acc[r].y * acc[r].y;
            s[2] += acc[r].z; sq[2] += acc[r].z * acc[r].z;
            s[3] += acc[r].w; sq[3] += acc[r].w * acc[r].w;
        }
    }
    __syncthreads();
    float* red = Zs;
#pragma unroll
    for (int i = 0; i < 4; i++) {
        red[rg * 128 + cg * 4 + i] = s[i];
        red[512 + rg * 128 + cg * 4 + i] = sq[i];
    }
    __syncthreads();
    if (tid < 128) {
        float ts = red[tid] + red[128 + tid] + red[256 + tid] + red[384 + tid];
        float tq = red[512 + tid] + red[640 + tid] + red[768 + tid] + red[896 + tid];
        atomicAdd(&g_stats[tid], ts);
        atomicAdd(&g_stats[128 + tid], tq);
    }
}

// ---------------------------------------------------------------------------
// Finalize BN stats -> scale/shift
// ---------------------------------------------------------------------------
__global__ void finalize_kernel(const float* __restrict__ g, const float* __restrict__ b,
                                int C, int statoff, int which, float nInv)
{
    int t = threadIdx.x;
    if (t >= C) return;
    float mean = g_stats[statoff + t] * nInv;
    float var = g_stats[statoff + C + t] * nInv - mean * mean;
    var = fmaxf(var, 0.f);
    float inv = rsqrtf(var + 1e-5f);
    float scale = __ldg(&g[t]) * inv;
    float shift = __ldg(&b[t]) - mean * scale;
    float* out = which ? g_bn2 : g_bn1;
    out[t] = scale;
    out[C + t] = shift;
}

// ---------------------------------------------------------------------------
// GEMM2 (R5 FFMA): t = relu(bn1(y1)) (128) -> y2 = t@W2 + b2 (64) -> g_agg,
// fused BN2 stats.
// ---------------------------------------------------------------------------
__global__ __launch_bounds__(128) void gemm2_kernel(
    const float* __restrict__ W2, const float* __restrict__ b2, int n)
{
    __shared__ float Ws[128 * 64];  // 32 KB
    __shared__ float Zs[32 * 128];  // 16 KB (reused for stats reduction)
    int tid = threadIdx.x;

    for (int i = tid; i < 2048; i += 128)
        ((float4*)Ws)[i] = ((const float4*)W2)[i];

    int r0 = blockIdx.x * 32;
    for (int i = tid; i < 1024; i += 128) {  // 32*128/4 float4
        int rr = i >> 5, cc = i & 31;
        int row = r0 + rr;
        float4 z = make_float4(0.f, 0.f, 0.f, 0.f);
        if (row < n) {
            float4 y = ((const float4*)g_y1)[(size_t)row * 32 + cc];
            float4 sc = ((const float4*)g_bn1)[cc];
            float4 sh = ((const float4*)g_bn1)[32 + cc];
            z.x = fmaxf(fmaf(y.x, sc.x, sh.x), 0.f);
            z.y = fmaxf(fmaf(y.y, sc.y, sh.y), 0.f);
            z.z = fmaxf(fmaf(y.z, sc.z, sh.z), 0.f);
            z.w = fmaxf(fmaf(y.w, sc.w, sh.w), 0.f);
        }
        ((float4*)Zs)[i] = z;
    }
    __syncthreads();

    int cg = tid & 31;
    int rg = tid >> 5;
    float2 bias = ((const float2*)b2)[cg];
    float2 acc[8];
#pragma unroll
    for (int r = 0; r < 8; r++) acc[r] = bias;

    for (int k = 0; k < 128; k++) {
        float2 w = ((const float2*)Ws)[k * 32 + cg];
#pragma unroll
        for (int r = 0; r < 8; r++) {
            float z = Zs[(rg * 8 + r) * 128 + k];
            acc[r].x = fmaf(z, w.x, acc[r].x);
            acc[r].y = fmaf(z, w.y, acc[r].y);
        }
    }

    float s[2] = {0.f, 0.f}, sq[2] = {0.f, 0.f};
#pragma unroll
    for (int r = 0; r < 8; r++) {
        int row = r0 + rg * 8 + r;
        if (row < n) {
            ((float2*)g_agg)[(size_t)row * 32 + cg] = acc[r];
            s[0] += acc[r].x; sq[0] += acc[r].x * acc[r].x;
            s[1] += acc[r].y; sq[1] += acc[r].y * acc[r].y;
        }
    }
    __syncthreads();
    float* red = Zs;
    red[rg * 64 + cg * 2 + 0] = s[0];
    red[rg * 64 + cg * 2 + 1] = s[1];
    red[256 + rg * 64 + cg * 2 + 0] = sq[0];
    red[256 + rg * 64 + cg * 2 + 1] = sq[1];
    __syncthreads();
    if (tid < 64) {
        float ts = red[tid] + red[64 + tid] + red[128 + tid] + red[192 + tid];
        float tq = red[256 + tid] + red[320 + tid] + red[384 + tid] + red[448 + tid];
        atomicAdd(&g_stats[256 + tid], ts);
        atomicAdd(&g_stats[320 + tid], tq);
    }
}

// ---------------------------------------------------------------------------
// BN2 apply. mode 0 (intermediate): relu, write g_h, zero g_agg for next layer.
// mode 1 (final): write nodeout + fused mean-pool red-adds.
// ---------------------------------------------------------------------------
__global__ __launch_bounds__(256) void bn2_apply_kernel(
    float* __restrict__ nodeout, const int* __restrict__ batch,
    float* __restrict__ gout, int n, int mode)
{
    int i = blockIdx.x * 256 + threadIdx.x;
    if (i >= n * 16) return;
    int c = i & 15;
    float4 y = ((const float4*)g_agg)[i];
    float4 sc = ((const float4*)g_bn2)[c];
    float4 sh = ((const float4*)g_bn2)[16 + c];
    float4 v;
    v.x = fmaf(y.x, sc.x, sh.x);
    v.y = fmaf(y.y, sc.y, sh.y);
    v.z = fmaf(y.z, sc.z, sh.z);
    v.w = fmaf(y.w, sc.w, sh.w);
    if (mode == 0) {
        v.x = fmaxf(v.x, 0.f); v.y = fmaxf(v.y, 0.f);
        v.z = fmaxf(v.z, 0.f); v.w = fmaxf(v.w, 0.f);
        ((float4*)g_h)[i] = v;
        ((float4*)g_agg)[i] = make_float4(0.f, 0.f, 0.f, 0.f);
    } else {
        ((float4*)nodeout)[i] = v;
        int nid = i >> 4;
        int b = __ldg(&batch[nid]);
        red_add_v4(gout + (size_t)b * 64 + c * 4, v);
        if (c == 0) atomicAdd(&g_cnt[b], 1.0f);
    }
}

__global__ __launch_bounds__(256) void divide_kernel(float* __restrict__ gout, int b)
{
    int i = blockIdx.x * 256 + threadIdx.x;
    if (i < b * 64) gout[i] = gout[i] / (g_cnt[i >> 6] + 1e-9f);
}

// ---------------------------------------------------------------------------
// Launch
// ---------------------------------------------------------------------------
extern "C" void kernel_launch(void* const* d_in, const int* in_sizes, int n_in,
                              void* d_out, int out_size)
{
    const float* atom_emb = (const float*)d_in[0];
    const float* bond_emb = (const float*)d_in[1];
    const float* eps      = (const float*)d_in[2];
    const float* W1       = (const float*)d_in[3];
    const float* b1       = (const float*)d_in[4];
    const float* bn1_g    = (const float*)d_in[5];
    const float* bn1_b    = (const float*)d_in[6];
    const float* W2       = (const float*)d_in[7];
    const float* b2       = (const float*)d_in[8];
    const float* bn2_g    = (const float*)d_in[9];
    const float* bn2_b    = (const float*)d_in[10];
    const int* x_feat     = (const int*)d_in[11];
    const int* edge_index = (const int*)d_in[12];
    const int* edge_attr  = (const int*)d_in[13];
    const int* batch      = (const int*)d_in[14];

    int n = in_sizes[11] / 9;
    int e = in_sizes[12] / 2;
    int b = out_size / 64 - n;
    float* nodeout = (float*)d_out;
    float* gout = nodeout + (size_t)n * 64;

    int nodeChunks = n * 16;
    int nodeGrid = (nodeChunks + 255) / 256;
    int edgeGrid = 1036;   // 7 CTAs x 148 SMs; grid-stride inside
    float nInv = 1.0f / (float)n;

    atom_kernel<<<nodeGrid, 256>>>(atom_emb, x_feat, n);
    prep_combo_kernel<<<(e + 255) / 256, 256>>>(edge_attr, e);
    clear_agg_kernel<<<nodeGrid, 256>>>(nodeChunks);
    {
        int poolClear = (b * 64 + 255) / 256;
        clear_pool_kernel<<<poolClear, 256>>>(gout, b);
    }

    for (int l = 0; l < 4; l++) {
        clear_stats_kernel<<<1, 384>>>();
        edge_kernel<<<edgeGrid, 256>>>(bond_emb + l * 1536, edge_index, e);
        gemm1_kernel<<<(n + 31) / 32, 128>>>(W1 + l * 64 * 128, b1 + l * 128, eps + l, n);
        finalize_kernel<<<1, 128>>>(bn1_g + l * 128, bn1_b + l * 128, 128, 0, 0, nInv);
        gemm2_kernel<<<(n + 31) / 32, 128>>>(W2 + l * 128 * 64, b2 + l * 64, n);
        finalize_kernel<<<1, 64>>>(bn2_g + l * 64, bn2_b + l * 64, 64, 256, 1, nInv);
        bn2_apply_kernel<<<nodeGrid, 256>>>(nodeout, batch, gout, n, (l == 3) ? 1 : 0);
    }

    int poolDiv = (b * 64 + 255) / 256;
    divide_kernel<<<poolDiv, 256>>>(gout, b);
}

// round 10
// speedup vs baseline: 2.0438x; 1.4462x over previous
#include <cuda_runtime.h>
#include <cstdint>

// ---------------------------------------------------------------------------
// GIN graph network, fp32. N=100000, E=1.25M, D=64, L=4, B=2048.
// GEMMs: B-stationary mma.sync tf32 3-pass (hi/lo split == fp32 accuracy),
// W fragments in registers, persistent grid-stride blocks, fused BN stats.
// Edge: combo-table + packed int4 metadata. Finalize folded into consumers.
// ---------------------------------------------------------------------------

#define MAXN 100000
#define MAXE 1250000
#define MAXB 2048

__device__ __align__(16) float g_h[(size_t)MAXN * 64];
__device__ __align__(16) float g_agg[(size_t)MAXN * 64];   // also reused as y2
__device__ __align__(16) float g_y1[(size_t)MAXN * 128];
__device__ __align__(16) float g_stats[384];  // [0:128) sum1 [128:256) sq1 [256:320) sum2 [320:384) sq2
__device__ float g_cnt[MAXB];
__device__ __align__(16) int4 g_meta[MAXE];   // (src, dst, combo, 0)

__device__ __forceinline__ void red_add_v4(float* addr, float4 v) {
    asm volatile("red.global.add.v4.f32 [%0], {%1,%2,%3,%4};"
                 :: "l"(addr), "f"(v.x), "f"(v.y), "f"(v.z), "f"(v.w)
                 : "memory");
}

// tf32 split: hi = fp32 with low 13 mantissa bits cleared (exact tf32), lo = x - hi
__device__ __forceinline__ float tf32_hi(float x) {
    return __uint_as_float(__float_as_uint(x) & 0xFFFFE000u);
}

// mma.sync m16n8k8 tf32: D += A*B (accumulate in place)
__device__ __forceinline__ void mma8f(float* d, float a0, float a1, float a2, float a3,
                                      float b0, float b1) {
    asm volatile(
        "mma.sync.aligned.m16n8k8.row.col.f32.tf32.tf32.f32 "
        "{%0,%1,%2,%3}, {%4,%5,%6,%7}, {%8,%9}, {%0,%1,%2,%3};"
        : "+f"(d[0]), "+f"(d[1]), "+f"(d[2]), "+f"(d[3])
        : "r"(__float_as_uint(a0)), "r"(__float_as_uint(a1)),
          "r"(__float_as_uint(a2)), "r"(__float_as_uint(a3)),
          "r"(__float_as_uint(b0)), "r"(__float_as_uint(b1)));
}

// ---------------------------------------------------------------------------
// Atom encoder
// ---------------------------------------------------------------------------
__global__ __launch_bounds__(256) void atom_kernel(
    const float* __restrict__ atom_emb, const int* __restrict__ x_feat, int n)
{
    int wi = blockIdx.x * 256 + threadIdx.x;
    int nid = wi >> 4;
    if (nid >= n) return;
    int c = wi & 15;
    const float4* ae = (const float4*)atom_emb;  // [9,128,16] float4
    float4 acc = make_float4(0.f, 0.f, 0.f, 0.f);
#pragma unroll
    for (int f = 0; f < 9; f++) {
        int idx = __ldg(&x_feat[nid * 9 + f]);
        float4 v = ae[(f * 128 + idx) * 16 + c];
        acc.x += v.x; acc.y += v.y; acc.z += v.z; acc.w += v.w;
    }
    ((float4*)g_h)[(size_t)nid * 16 + c] = acc;
}

// ---------------------------------------------------------------------------
// One-time prep: pack (src, dst, combo) per edge
// ---------------------------------------------------------------------------
__global__ __launch_bounds__(256) void prep_meta_kernel(
    const int* __restrict__ edge_index, const int* __restrict__ edge_attr, int e)
{
    int i = blockIdx.x * 256 + threadIdx.x;
    if (i >= e) return;
    int a0 = edge_attr[3 * i + 0];
    int a1 = edge_attr[3 * i + 1];
    int a2 = edge_attr[3 * i + 2];
    g_meta[i] = make_int4(edge_index[i], edge_index[e + i], a0 * 25 + a1 * 5 + a2, 0);
}

// ---------------------------------------------------------------------------
// Clears
// ---------------------------------------------------------------------------
__global__ __launch_bounds__(256) void clear_agg_kernel(int count4)
{
    int i = blockIdx.x * 256 + threadIdx.x;
    if (i < count4) ((float4*)g_agg)[i] = make_float4(0.f, 0.f, 0.f, 0.f);
}
__global__ __launch_bounds__(256) void clear_pool_kernel(float* __restrict__ gout, int b)
{
    int i = blockIdx.x * 256 + threadIdx.x;
    if (i < b * 64) gout[i] = 0.f;
    if (i < b) g_cnt[i] = 0.f;
}

// ---------------------------------------------------------------------------
// Edge kernel: 125-combo table in smem; grid-stride; one int4 broadcast load
// per edge group. Block 0 zeroes g_stats for this layer (consumed later).
// ---------------------------------------------------------------------------
__global__ __launch_bounds__(256) void edge_kernel(
    const float* __restrict__ bond_emb_l, int e)
{
    __shared__ __align__(16) float table[125 * 64];   // 31.25 KB

    if (blockIdx.x == 0 && threadIdx.x < 128) {
        ((float*)g_stats)[threadIdx.x] = 0.f;
        ((float*)g_stats)[128 + threadIdx.x] = 0.f;
        ((float*)g_stats)[256 + threadIdx.x] = 0.f;
    }

    const float4* b4 = (const float4*)bond_emb_l;     // [3,8,16] float4
    for (int t = threadIdx.x; t < 2000; t += 256) {   // 125*16 float4
        int combo = t >> 4, c4 = t & 15;
        int a0 = combo / 25;
        int rr = combo - a0 * 25;
        int a1 = rr / 5;
        int a2 = rr - a1 * 5;
        float4 v0 = b4[a0 * 16 + c4];
        float4 v1 = b4[(8 + a1) * 16 + c4];
        float4 v2 = b4[(16 + a2) * 16 + c4];
        float4 s;
        s.x = v0.x + v1.x + v2.x;
        s.y = v0.y + v1.y + v2.y;
        s.z = v0.z + v1.z + v2.z;
        s.w = v0.w + v1.w + v2.w;
        ((float4*)table)[t] = s;
    }
    __syncthreads();

    int c = threadIdx.x & 15;
    long long total = (long long)e * 16;
    long long stride = (long long)gridDim.x * 256;
    for (long long item = (long long)blockIdx.x * 256 + threadIdx.x;
         item < total; item += stride) {
        int eidx = (int)(item >> 4);
        int4 md = __ldg(&g_meta[eidx]);
        float4 ev = ((const float4*)table)[md.z * 16 + c];
        float4 hv = ((const float4*)g_h)[(size_t)md.x * 16 + c];
        float4 m;
        m.x = fmaxf(hv.x + ev.x, 0.f);
        m.y = fmaxf(hv.y + ev.y, 0.f);
        m.z = fmaxf(hv.z + ev.z, 0.f);
        m.w = fmaxf(hv.w + ev.w, 0.f);
        red_add_v4(g_agg + (size_t)md.y * 64 + c * 4, m);
    }
}

// ---------------------------------------------------------------------------
// GEMM1 (tensor, B-stationary): z = (1+eps)*h + agg [16-row tiles x 64K]
// -> y1 = z@W1 + b1 [x128N]. W1 fragments (hi/lo) in registers. Double-
// buffered A staging. BN1 stats accumulated in registers, reduced at end.
// Warp w covers cols [w*16, w*16+16) (2 n8-tiles).
// ---------------------------------------------------------------------------
__global__ __launch_bounds__(256, 2) void gemm1_tc_kernel(
    const float* __restrict__ W1, const float* __restrict__ b1,
    const float* __restrict__ epsp, int n, int ntiles)
{
    __shared__ float Zh[2][16][68];
    __shared__ float Zl[2][16][68];

    int tid = threadIdx.x;
    int wid = tid >> 5;
    int lane = tid & 31;
    int g = lane >> 2, tt = lane & 3;
    int nt0 = wid * 16;

    // W fragments in registers: wh/wl[ks][t2][reg]
    float wh[8][2][2], wl[8][2][2];
#pragma unroll
    for (int ks = 0; ks < 8; ks++)
#pragma unroll
        for (int t2 = 0; t2 < 2; t2++) {
            int col = nt0 + t2 * 8 + g;
            int k0 = ks * 8 + tt;
            float w0 = __ldg(&W1[k0 * 128 + col]);
            float w1 = __ldg(&W1[(k0 + 4) * 128 + col]);
            wh[ks][t2][0] = tf32_hi(w0); wl[ks][t2][0] = w0 - wh[ks][t2][0];
            wh[ks][t2][1] = tf32_hi(w1); wl[ks][t2][1] = w1 - wh[ks][t2][1];
        }
    float2 bias[2];
#pragma unroll
    for (int t2 = 0; t2 < 2; t2++)
        bias[t2] = *(const float2*)(b1 + nt0 + t2 * 8 + tt * 2);

    float epsv = 1.0f + __ldg(epsp);
    int srr = tid >> 4, sc4 = tid & 15;   // staging: row, float4-col

    float sA[2][2] = {{0.f,0.f},{0.f,0.f}}, qA[2][2] = {{0.f,0.f},{0.f,0.f}};

    // prefetch first tile
    float4 ph = make_float4(0.f,0.f,0.f,0.f), pa = ph;
    int t = blockIdx.x;
    if (t < ntiles) {
        int row = t * 16 + srr;
        if (row < n) {
            ph = ((const float4*)g_h)[(size_t)row * 16 + sc4];
            pa = ((const float4*)g_agg)[(size_t)row * 16 + sc4];
        }
    }
    int buf = 0;
    for (; t < ntiles; t += gridDim.x) {
        // stage current tile from prefetched regs
        {
            float4 z;
            z.x = fmaf(epsv, ph.x, pa.x);
            z.y = fmaf(epsv, ph.y, pa.y);
            z.z = fmaf(epsv, ph.z, pa.z);
            z.w = fmaf(epsv, ph.w, pa.w);
            float* dh = &Zh[buf][srr][sc4 * 4];
            float* dl = &Zl[buf][srr][sc4 * 4];
            float h0 = tf32_hi(z.x), h1 = tf32_hi(z.y), h2 = tf32_hi(z.z), h3 = tf32_hi(z.w);
            dh[0] = h0; dh[1] = h1; dh[2] = h2; dh[3] = h3;
            dl[0] = z.x - h0; dl[1] = z.y - h1; dl[2] = z.z - h2; dl[3] = z.w - h3;
        }
        __syncthreads();

        // prefetch next tile
        int tn = t + gridDim.x;
        ph = make_float4(0.f,0.f,0.f,0.f); pa = ph;
        if (tn < ntiles) {
            int row = tn * 16 + srr;
            if (row < n) {
                ph = ((const float4*)g_h)[(size_t)row * 16 + sc4];
                pa = ((const float4*)g_agg)[(size_t)row * 16 + sc4];
            }
        }

        // compute
        float acc[2][4] = {{0.f,0.f,0.f,0.f},{0.f,0.f,0.f,0.f}};
#pragma unroll
        for (int ks = 0; ks < 8; ks++) {
            int kc = ks * 8 + tt;
            float ah0 = Zh[buf][g][kc],     ah1 = Zh[buf][g + 8][kc];
            float ah2 = Zh[buf][g][kc + 4], ah3 = Zh[buf][g + 8][kc + 4];
            float al0 = Zl[buf][g][kc],     al1 = Zl[buf][g + 8][kc];
            float al2 = Zl[buf][g][kc + 4], al3 = Zl[buf][g + 8][kc + 4];
#pragma unroll
            for (int t2 = 0; t2 < 2; t2++) {
                mma8f(acc[t2], ah0, ah1, ah2, ah3, wh[ks][t2][0], wh[ks][t2][1]);
                mma8f(acc[t2], ah0, ah1, ah2, ah3, wl[ks][t2][0], wl[ks][t2][1]);
                mma8f(acc[t2], al0, al1, al2, al3, wh[ks][t2][0], wh[ks][t2][1]);
            }
        }

        // epilogue: bias + store + local stats
        int r0 = t * 16;
        int rA = r0 + g, rB = r0 + g + 8;
#pragma unroll
        for (int t2 = 0; t2 < 2; t2++) {
            int col = nt0 + t2 * 8 + tt * 2;
            float e0 = acc[t2][0] + bias[t2].x, o0 = acc[t2][1] + bias[t2].y;
            float e1 = acc[t2][2] + bias[t2].x, o1 = acc[t2][3] + bias[t2].y;
            if (rA < n) {
                *(float2*)(g_y1 + (size_t)rA * 128 + col) = make_float2(e0, o0);
                sA[t2][0] += e0; qA[t2][0] += e0 * e0;
                sA[t2][1] += o0; qA[t2][1] += o0 * o0;
            }
            if (rB < n) {
                *(float2*)(g_y1 + (size_t)rB * 128 + col) = make_float2(e1, o1);
                sA[t2][0] += e1; qA[t2][0] += e1 * e1;
                sA[t2][1] += o1; qA[t2][1] += o1 * o1;
            }
        }
        buf ^= 1;
    }

    // final stats reduce over g (lane bits 2,3,4)
#pragma unroll
    for (int t2 = 0; t2 < 2; t2++)
#pragma unroll
        for (int j = 0; j < 2; j++) {
#pragma unroll
            for (int off = 4; off < 32; off <<= 1) {
                sA[t2][j] += __shfl_xor_sync(0xffffffffu, sA[t2][j], off);
                qA[t2][j] += __shfl_xor_sync(0xffffffffu, qA[t2][j], off);
            }
        }
    if (g == 0) {
#pragma unroll
        for (int t2 = 0; t2 < 2; t2++) {
            int col = nt0 + t2 * 8 + tt * 2;
            atomicAdd(&g_stats[col], sA[t2][0]);
            atomicAdd(&g_stats[col + 1], sA[t2][1]);
            atomicAdd(&g_stats[128 + col], qA[t2][0]);
            atomicAdd(&g_stats[128 + col + 1], qA[t2][1]);
        }
    }
}

// ---------------------------------------------------------------------------
// GEMM2 (tensor, B-stationary): t = relu(bn1(y1)) [16-row tiles x 128K]
// -> y2 = t@W2 + b2 [x64N] -> g_agg. BN1 computed per block from g_stats.
// Warp w covers cols [w*8, w*8+8) (1 n8-tile). BN2 stats fused.
// ---------------------------------------------------------------------------
__global__ __launch_bounds__(256, 2) void gemm2_tc_kernel(
    const float* __restrict__ W2, const float* __restrict__ b2,
    const float* __restrict__ bn1_g, const float* __restrict__ bn1_b,
    float nInv, int n, int ntiles)
{
    __shared__ float Zh[2][16][132];
    __shared__ float Zl[2][16][132];
    __shared__ __align__(16) float bsc[128];
    __shared__ __align__(16) float bsh[128];

    int tid = threadIdx.x;
    int wid = tid >> 5;
    int lane = tid & 31;
    int g = lane >> 2, tt = lane & 3;
    int nt0 = wid * 8;

    // bn1 scale/shift from global stats
    if (tid < 128) {
        float mean = g_stats[tid] * nInv;
        float var = fmaxf(g_stats[128 + tid] * nInv - mean * mean, 0.f);
        float inv = rsqrtf(var + 1e-5f);
        float sc = __ldg(&bn1_g[tid]) * inv;
        bsc[tid] = sc;
        bsh[tid] = __ldg(&bn1_b[tid]) - mean * sc;
    }

    // W2 fragments in registers: [ks][reg]
    float wh[16][2], wl[16][2];
#pragma unroll
    for (int ks = 0; ks < 16; ks++) {
        int col = nt0 + g;
        int k0 = ks * 8 + tt;
        float w0 = __ldg(&W2[k0 * 64 + col]);
        float w1 = __ldg(&W2[(k0 + 4) * 64 + col]);
        wh[ks][0] = tf32_hi(w0); wl[ks][0] = w0 - wh[ks][0];
        wh[ks][1] = tf32_hi(w1); wl[ks][1] = w1 - wh[ks][1];
    }
    float2 bias = *(const float2*)(b2 + nt0 + tt * 2);

    int srr = tid >> 4, sc4b = (tid & 15) * 2;  // staging: row, 2 float4 cols

    float sA[2] = {0.f, 0.f}, qA[2] = {0.f, 0.f};
    __syncthreads();   // bsc/bsh ready

    // prefetch first tile (2 float4 per thread)
    float4 p0 = make_float4(0.f,0.f,0.f,0.f), p1 = p0;
    int t = blockIdx.x;
    if (t < ntiles) {
        int row = t * 16 + srr;
        if (row < n) {
            p0 = ((const float4*)g_y1)[(size_t)row * 32 + sc4b];
            p1 = ((const float4*)g_y1)[(size_t)row * 32 + sc4b + 1];
        }
    }
    int buf = 0;
    for (; t < ntiles; t += gridDim.x) {
        // stage: apply bn1 + relu + split
        {
#pragma unroll
            for (int j = 0; j < 2; j++) {
                float4 y = j ? p1 : p0;
                int c4 = sc4b + j;
                float4 sc = ((const float4*)bsc)[c4];
                float4 sh = ((const float4*)bsh)[c4];
                float z0 = fmaxf(fmaf(y.x, sc.x, sh.x), 0.f);
                float z1 = fmaxf(fmaf(y.y, sc.y, sh.y), 0.f);
                float z2 = fmaxf(fmaf(y.z, sc.z, sh.z), 0.f);
                float z3 = fmaxf(fmaf(y.w, sc.w, sh.w), 0.f);
                float* dh = &Zh[buf][srr][c4 * 4];
                float* dl = &Zl[buf][srr][c4 * 4];
                float h0 = tf32_hi(z0), h1 = tf32_hi(z1), h2 = tf32_hi(z2), h3 = tf32_hi(z3);
                dh[0] = h0; dh[1] = h1; dh[2] = h2; dh[3] = h3;
                dl[0] = z0 - h0; dl[1] = z1 - h1; dl[2] = z2 - h2; dl[3] = z3 - h3;
            }
        }
        __syncthreads();

        // prefetch next
        int tn = t + gridDim.x;
        p0 = make_float4(0.f,0.f,0.f,0.f); p1 = p0;
        if (tn < ntiles) {
            int row = tn * 16 + srr;
            if (row < n) {
                p0 = ((const float4*)g_y1)[(size_t)row * 32 + sc4b];
                p1 = ((const float4*)g_y1)[(size_t)row * 32 + sc4b + 1];
            }
        }

        float acc[4] = {0.f, 0.f, 0.f, 0.f};
#pragma unroll
        for (int ks = 0; ks < 16; ks++) {
            int kc = ks * 8 + tt;
            float ah0 = Zh[buf][g][kc],     ah1 = Zh[buf][g + 8][kc];
            float ah2 = Zh[buf][g][kc + 4], ah3 = Zh[buf][g + 8][kc + 4];
            float al0 = Zl[buf][g][kc],     al1 = Zl[buf][g + 8][kc];
            float al2 = Zl[buf][g][kc + 4], al3 = Zl[buf][g + 8][kc + 4];
            mma8f(acc, ah0, ah1, ah2, ah3, wh[ks][0], wh[ks][1]);
            mma8f(acc, ah0, ah1, ah2, ah3, wl[ks][0], wl[ks][1]);
            mma8f(acc, al0, al1, al2, al3, wh[ks][0], wh[ks][1]);
        }

        int r0 = t * 16;
        int rA = r0 + g, rB = r0 + g + 8;
        int col = nt0 + tt * 2;
        float e0 = acc[0] + bias.x, o0 = acc[1] + bias.y;
        float e1 = acc[2] + bias.x, o1 = acc[3] + bias.y;
        if (rA < n) {
            *(float2*)(g_agg + (size_t)rA * 64 + col) = make_float2(e0, o0);
            sA[0] += e0; qA[0] += e0 * e0;
            sA[1] += o0; qA[1] += o0 * o0;
        }
        if (rB < n) {
            *(float2*)(g_agg + (size_t)rB * 64 + col) = make_float2(e1, o1);
            sA[0] += e1; qA[0] += e1 * e1;
            sA[1] += o1; qA[1] += o1 * o1;
        }
        buf ^= 1;
    }

#pragma unroll
    for (int j = 0; j < 2; j++) {
#pragma unroll
        for (int off = 4; off < 32; off <<= 1) {
            sA[j] += __shfl_xor_sync(0xffffffffu, sA[j], off);
            qA[j] += __shfl_xor_sync(0xffffffffu, qA[j], off);
        }
    }
    if (g == 0) {
        int col = nt0 + tt * 2;
        atomicAdd(&g_stats[256 + col], sA[0]);
        atomicAdd(&g_stats[256 + col + 1], sA[1]);
        atomicAdd(&g_stats[320 + col], qA[0]);
        atomicAdd(&g_stats[320 + col + 1], qA[1]);
    }
}

// ---------------------------------------------------------------------------
// BN2 apply. Computes bn2 scale/shift per block from g_stats.
// mode 0: relu, write g_h, zero g_agg. mode 1: write nodeout + fused pooling.
// ---------------------------------------------------------------------------
__global__ __launch_bounds__(256) void bn2_apply_kernel(
    const float* __restrict__ bn2_g, const float* __restrict__ bn2_b,
    float* __restrict__ nodeout, const int* __restrict__ batch,
    float* __restrict__ gout, float nInv, int n, int mode)
{
    __shared__ __align__(16) float bsc[64];
    __shared__ __align__(16) float bsh[64];
    if (threadIdx.x < 64) {
        int t = threadIdx.x;
        float mean = g_stats[256 + t] * nInv;
        float var = fmaxf(g_stats[320 + t] * nInv - mean * mean, 0.f);
        float inv = rsqrtf(var + 1e-5f);
        float sc = __ldg(&bn2_g[t]) * inv;
        bsc[t] = sc;
        bsh[t] = __ldg(&bn2_b[t]) - mean * sc;
    }
    __syncthreads();

    int i = blockIdx.x * 256 + threadIdx.x;
    if (i >= n * 16) return;
    int c = i & 15;
    float4 y = ((const float4*)g_agg)[i];
    float4 sc = ((const float4*)bsc)[c];
    float4 sh = ((const float4*)bsh)[c];
    float4 v;
    v.x = fmaf(y.x, sc.x, sh.x);
    v.y = fmaf(y.y, sc.y, sh.y);
    v.z = fmaf(y.z, sc.z, sh.z);
    v.w = fmaf(y.w, sc.w, sh.w);
    if (mode == 0) {
        v.x = fmaxf(v.x, 0.f); v.y = fmaxf(v.y, 0.f);
        v.z = fmaxf(v.z, 0.f); v.w = fmaxf(v.w, 0.f);
        ((float4*)g_h)[i] = v;
        ((float4*)g_agg)[i] = make_float4(0.f, 0.f, 0.f, 0.f);
    } else {
        ((float4*)nodeout)[i] = v;
        int nid = i >> 4;
        int b = __ldg(&batch[nid]);
        red_add_v4(gout + (size_t)b * 64 + c * 4, v);
        if (c == 0) atomicAdd(&g_cnt[b], 1.0f);
    }
}

__global__ __launch_bounds__(256) void divide_kernel(float* __restrict__ gout, int b)
{
    int i = blockIdx.x * 256 + threadIdx.x;
    if (i < b * 64) gout[i] = gout[i] / (g_cnt[i >> 6] + 1e-9f);
}

// ---------------------------------------------------------------------------
// Launch
// ---------------------------------------------------------------------------
extern "C" void kernel_launch(void* const* d_in, const int* in_sizes, int n_in,
                              void* d_out, int out_size)
{
    const float* atom_emb = (const float*)d_in[0];
    const float* bond_emb = (const float*)d_in[1];
    const float* eps      = (const float*)d_in[2];
    const float* W1       = (const float*)d_in[3];
    const float* b1       = (const float*)d_in[4];
    const float* bn1_g    = (const float*)d_in[5];
    const float* bn1_b    = (const float*)d_in[6];
    const float* W2       = (const float*)d_in[7];
    const float* b2       = (const float*)d_in[8];
    const float* bn2_g    = (const float*)d_in[9];
    const float* bn2_b    = (const float*)d_in[10];
    const int* x_feat     = (const int*)d_in[11];
    const int* edge_index = (const int*)d_in[12];
    const int* edge_attr  = (const int*)d_in[13];
    const int* batch      = (const int*)d_in[14];

    int n = in_sizes[11] / 9;
    int e = in_sizes[12] / 2;
    int b = out_size / 64 - n;
    float* nodeout = (float*)d_out;
    float* gout = nodeout + (size_t)n * 64;

    int nodeChunks = n * 16;
    int nodeGrid = (nodeChunks + 255) / 256;
    int edgeGrid = 1036;
    int ntiles = (n + 15) / 16;
    int gemmGrid = 296;   // 2 blocks/SM x 148 SMs
    float nInv = 1.0f / (float)n;

    atom_kernel<<<nodeGrid, 256>>>(atom_emb, x_feat, n);
    prep_meta_kernel<<<(e + 255) / 256, 256>>>(edge_index, edge_attr, e);
    clear_agg_kernel<<<nodeGrid, 256>>>(nodeChunks);
    clear_pool_kernel<<<(b * 64 + 255) / 256, 256>>>(gout, b);

    for (int l = 0; l < 4; l++) {
        edge_kernel<<<edgeGrid, 256>>>(bond_emb + l * 1536, e);
        gemm1_tc_kernel<<<gemmGrid, 256>>>(W1 + l * 64 * 128, b1 + l * 128, eps + l, n, ntiles);
        gemm2_tc_kernel<<<gemmGrid, 256>>>(W2 + l * 128 * 64, b2 + l * 64,
                                           bn1_g + l * 128, bn1_b + l * 128, nInv, n, ntiles);
        bn2_apply_kernel<<<nodeGrid, 256>>>(bn2_g + l * 64, bn2_b + l * 64,
                                            nodeout, batch, gout, nInv, n, (l == 3) ? 1 : 0);
    }

    divide_kernel<<<(b * 64 + 255) / 256, 256>>>(gout, b);
}

// round 11
// speedup vs baseline: 2.2891x; 1.1200x over previous
#include <cuda_runtime.h>
#include <cstdint>

// ---------------------------------------------------------------------------
// GIN graph network, fp32. N=100000, E=1.25M, D=64, L=4, B=2048.
// Edge aggregation via one-time CSR-by-dst (no atomics in the hot loop):
// warp-per-node register accumulation writes z = (1+eps)*h + agg directly.
// GEMMs: B-stationary mma.sync tf32 3-pass (hi/lo split == fp32 accuracy).
// ---------------------------------------------------------------------------

#define MAXN 100000
#define MAXE 1250000
#define MAXB 2048

__device__ __align__(16) float g_h[(size_t)MAXN * 64];
__device__ __align__(16) float g_agg[(size_t)MAXN * 64];   // z buffer / y2 buffer
__device__ __align__(16) float g_y1[(size_t)MAXN * 128];
__device__ __align__(16) float g_stats[384];  // [0:128) sum1 [128:256) sq1 [256:320) sum2 [320:384) sq2
__device__ float g_cnt[MAXB];
__device__ int g_off[MAXN + 1];
__device__ int g_cur[MAXN];
__device__ int g_bsum[128];
__device__ __align__(8) int2 g_csr[MAXE];     // (src, combo) grouped by dst

__device__ __forceinline__ void red_add_v4(float* addr, float4 v) {
    asm volatile("red.global.add.v4.f32 [%0], {%1,%2,%3,%4};"
                 :: "l"(addr), "f"(v.x), "f"(v.y), "f"(v.z), "f"(v.w)
                 : "memory");
}

// tf32 split: hi = fp32 with low 13 mantissa bits cleared (exact tf32), lo = x - hi
__device__ __forceinline__ float tf32_hi(float x) {
    return __uint_as_float(__float_as_uint(x) & 0xFFFFE000u);
}

// mma.sync m16n8k8 tf32: D += A*B (accumulate in place)
__device__ __forceinline__ void mma8f(float* d, float a0, float a1, float a2, float a3,
                                      float b0, float b1) {
    asm volatile(
        "mma.sync.aligned.m16n8k8.row.col.f32.tf32.tf32.f32 "
        "{%0,%1,%2,%3}, {%4,%5,%6,%7}, {%8,%9}, {%0,%1,%2,%3};"
        : "+f"(d[0]), "+f"(d[1]), "+f"(d[2]), "+f"(d[3])
        : "r"(__float_as_uint(a0)), "r"(__float_as_uint(a1)),
          "r"(__float_as_uint(a2)), "r"(__float_as_uint(a3)),
          "r"(__float_as_uint(b0)), "r"(__float_as_uint(b1)));
}

// ---------------------------------------------------------------------------
// Atom encoder
// ---------------------------------------------------------------------------
__global__ __launch_bounds__(256) void atom_kernel(
    const float* __restrict__ atom_emb, const int* __restrict__ x_feat, int n)
{
    int wi = blockIdx.x * 256 + threadIdx.x;
    int nid = wi >> 4;
    if (nid >= n) return;
    int c = wi & 15;
    const float4* ae = (const float4*)atom_emb;  // [9,128,16] float4
    float4 acc = make_float4(0.f, 0.f, 0.f, 0.f);
#pragma unroll
    for (int f = 0; f < 9; f++) {
        int idx = __ldg(&x_feat[nid * 9 + f]);
        float4 v = ae[(f * 128 + idx) * 16 + c];
        acc.x += v.x; acc.y += v.y; acc.z += v.z; acc.w += v.w;
    }
    ((float4*)g_h)[(size_t)nid * 16 + c] = acc;
}

// ---------------------------------------------------------------------------
// CSR build (one-time): histogram -> scan -> scatter
// ---------------------------------------------------------------------------
__global__ __launch_bounds__(256) void clear_off_kernel(int n)
{
    int i = blockIdx.x * 256 + threadIdx.x;
    if (i <= n) g_off[i] = 0;
}

__global__ __launch_bounds__(256) void hist_kernel(
    const int* __restrict__ edge_index, int e)
{
    int i = blockIdx.x * 256 + threadIdx.x;
    if (i >= e) return;
    atomicAdd(&g_off[__ldg(&edge_index[e + i]) + 1], 1);
}

// k1: per-1024-chunk sums of g_off[1..n]
__global__ __launch_bounds__(1024) void scan_partial_kernel(int n)
{
    int tid = threadIdx.x;
    int j = 1 + blockIdx.x * 1024 + tid;
    int v = (j <= n) ? g_off[j] : 0;
    __shared__ int ws[32];
    int lane = tid & 31, w = tid >> 5;
#pragma unroll
    for (int off = 16; off > 0; off >>= 1) v += __shfl_down_sync(0xffffffffu, v, off);
    if (lane == 0) ws[w] = v;
    __syncthreads();
    if (w == 0) {
        int t = ws[lane];
#pragma unroll
        for (int off = 16; off > 0; off >>= 1) t += __shfl_down_sync(0xffffffffu, t, off);
        if (lane == 0) g_bsum[blockIdx.x] = t;
    }
}

// k2: exclusive scan of chunk sums (single thread; ~100 elements)
__global__ void scan_bsums_kernel(int nblocks)
{
    if (threadIdx.x == 0) {
        int carry = 0;
        for (int b = 0; b < nblocks; b++) {
            int t = g_bsum[b];
            g_bsum[b] = carry;
            carry += t;
        }
    }
}

// k3: block inclusive scan + chunk prefix -> g_off[j]
__global__ __launch_bounds__(1024) void scan_final_kernel(int n)
{
    int tid = threadIdx.x;
    int j = 1 + blockIdx.x * 1024 + tid;
    int v = (j <= n) ? g_off[j] : 0;
    __shared__ int ws[32];
    int lane = tid & 31, w = tid >> 5;
    int x = v;
#pragma unroll
    for (int off = 1; off < 32; off <<= 1) {
        int t = __shfl_up_sync(0xffffffffu, x, off);
        if (lane >= off) x += t;
    }
    if (lane == 31) ws[w] = x;
    __syncthreads();
    if (w == 0) {
        int t = ws[lane];
#pragma unroll
        for (int off = 1; off < 32; off <<= 1) {
            int u = __shfl_up_sync(0xffffffffu, t, off);
            if (lane >= off) t += u;
        }
        ws[lane] = t;
    }
    __syncthreads();
    int pref = (w > 0) ? ws[w - 1] : 0;
    if (j <= n) g_off[j] = x + pref + g_bsum[blockIdx.x];
}

__global__ __launch_bounds__(256) void copy_cur_kernel(int n)
{
    int i = blockIdx.x * 256 + threadIdx.x;
    if (i < n) g_cur[i] = g_off[i];
}

__global__ __launch_bounds__(256) void scatter_kernel(
    const int* __restrict__ edge_index, const int* __restrict__ edge_attr, int e)
{
    int i = blockIdx.x * 256 + threadIdx.x;
    if (i >= e) return;
    int src = __ldg(&edge_index[i]);
    int dst = __ldg(&edge_index[e + i]);
    int a0 = __ldg(&edge_attr[3 * i + 0]);
    int a1 = __ldg(&edge_attr[3 * i + 1]);
    int a2 = __ldg(&edge_attr[3 * i + 2]);
    int pos = atomicAdd(&g_cur[dst], 1);
    g_csr[pos] = make_int2(src, a0 * 25 + a1 * 5 + a2);
}

__global__ __launch_bounds__(256) void clear_pool_kernel(float* __restrict__ gout, int b)
{
    int i = blockIdx.x * 256 + threadIdx.x;
    if (i < b * 64) gout[i] = 0.f;
    if (i < b) g_cnt[i] = 0.f;
}

// ---------------------------------------------------------------------------
// Edge kernel (CSR): warp-per-node. lane = float2 chunk of 64 cols.
// acc = sum relu(h[src] + table[combo]); writes z = (1+eps)*h[nid] + acc.
// Block 0 zeroes g_stats for this layer.
// ---------------------------------------------------------------------------
__global__ __launch_bounds__(256) void edge_csr_kernel(
    const float* __restrict__ bond_emb_l, const float* __restrict__ epsp, int n)
{
    __shared__ __align__(16) float table[125 * 64];   // 31.25 KB

    if (blockIdx.x == 0 && threadIdx.x < 128) {
        g_stats[threadIdx.x] = 0.f;
        g_stats[128 + threadIdx.x] = 0.f;
        g_stats[256 + threadIdx.x] = 0.f;
    }

    const float4* b4 = (const float4*)bond_emb_l;     // [3,8,16] float4
    for (int t = threadIdx.x; t < 2000; t += 256) {   // 125*16 float4
        int combo = t >> 4, c4 = t & 15;
        int a0 = combo / 25;
        int rr = combo - a0 * 25;
        int a1 = rr / 5;
        int a2 = rr - a1 * 5;
        float4 v0 = b4[a0 * 16 + c4];
        float4 v1 = b4[(8 + a1) * 16 + c4];
        float4 v2 = b4[(16 + a2) * 16 + c4];
        float4 s;
        s.x = v0.x + v1.x + v2.x;
        s.y = v0.y + v1.y + v2.y;
        s.z = v0.z + v1.z + v2.z;
        s.w = v0.w + v1.w + v2.w;
        ((float4*)table)[t] = s;
    }
    __syncthreads();

    float epsv = 1.0f + __ldg(epsp);
    int lane = threadIdx.x & 31;
    int w = threadIdx.x >> 5;
    const float2* th2 = (const float2*)table;
    const float2* h2 = (const float2*)g_h;

    for (int nid = blockIdx.x * 8 + w; nid < n; nid += gridDim.x * 8) {
        int s = __ldg(&g_off[nid]);
        int epos = __ldg(&g_off[nid + 1]);
        float2 a0 = make_float2(0.f, 0.f), a1 = make_float2(0.f, 0.f);
        int j = s;
        for (; j + 2 <= epos; j += 2) {
            int2 m0 = __ldg(&g_csr[j]);
            int2 m1 = __ldg(&g_csr[j + 1]);
            float2 e0 = th2[m0.y * 32 + lane];
            float2 e1 = th2[m1.y * 32 + lane];
            float2 h0 = h2[(size_t)m0.x * 32 + lane];
            float2 h1 = h2[(size_t)m1.x * 32 + lane];
            a0.x += fmaxf(h0.x + e0.x, 0.f);
            a0.y += fmaxf(h0.y + e0.y, 0.f);
            a1.x += fmaxf(h1.x + e1.x, 0.f);
            a1.y += fmaxf(h1.y + e1.y, 0.f);
        }
        if (j < epos) {
            int2 m0 = __ldg(&g_csr[j]);
            float2 e0 = th2[m0.y * 32 + lane];
            float2 h0 = h2[(size_t)m0.x * 32 + lane];
            a0.x += fmaxf(h0.x + e0.x, 0.f);
            a0.y += fmaxf(h0.y + e0.y, 0.f);
        }
        float2 hd = h2[(size_t)nid * 32 + lane];
        float2 z;
        z.x = fmaf(epsv, hd.x, a0.x + a1.x);
        z.y = fmaf(epsv, hd.y, a0.y + a1.y);
        ((float2*)g_agg)[(size_t)nid * 32 + lane] = z;
    }
}

// ---------------------------------------------------------------------------
// GEMM1 (tensor, B-stationary): z (g_agg) [16-row tiles x 64K] -> y1 = z@W1+b1
// [x128N]. W1 fragments (hi/lo) in registers. Fused BN1 stats.
// ---------------------------------------------------------------------------
__global__ __launch_bounds__(256, 2) void gemm1_tc_kernel(
    const float* __restrict__ W1, const float* __restrict__ b1, int n, int ntiles)
{
    __shared__ float Zh[2][16][68];
    __shared__ float Zl[2][16][68];

    int tid = threadIdx.x;
    int wid = tid >> 5;
    int lane = tid & 31;
    int g = lane >> 2, tt = lane & 3;
    int nt0 = wid * 16;

    float wh[8][2][2], wl[8][2][2];
#pragma unroll
    for (int ks = 0; ks < 8; ks++)
#pragma unroll
        for (int t2 = 0; t2 < 2; t2++) {
            int col = nt0 + t2 * 8 + g;
            int k0 = ks * 8 + tt;
            float w0 = __ldg(&W1[k0 * 128 + col]);
            float w1 = __ldg(&W1[(k0 + 4) * 128 + col]);
            wh[ks][t2][0] = tf32_hi(w0); wl[ks][t2][0] = w0 - wh[ks][t2][0];
            wh[ks][t2][1] = tf32_hi(w1); wl[ks][t2][1] = w1 - wh[ks][t2][1];
        }
    float2 bias[2];
#pragma unroll
    for (int t2 = 0; t2 < 2; t2++)
        bias[t2] = *(const float2*)(b1 + nt0 + t2 * 8 + tt * 2);

    int srr = tid >> 4, sc4 = tid & 15;

    float sA[2][2] = {{0.f,0.f},{0.f,0.f}}, qA[2][2] = {{0.f,0.f},{0.f,0.f}};

    float4 pa = make_float4(0.f,0.f,0.f,0.f);
    int t = blockIdx.x;
    if (t < ntiles) {
        int row = t * 16 + srr;
        if (row < n) pa = ((const float4*)g_agg)[(size_t)row * 16 + sc4];
    }
    int buf = 0;
    for (; t < ntiles; t += gridDim.x) {
        {
            float* dh = &Zh[buf][srr][sc4 * 4];
            float* dl = &Zl[buf][srr][sc4 * 4];
            float h0 = tf32_hi(pa.x), h1 = tf32_hi(pa.y), h2 = tf32_hi(pa.z), h3 = tf32_hi(pa.w);
            dh[0] = h0; dh[1] = h1; dh[2] = h2; dh[3] = h3;
            dl[0] = pa.x - h0; dl[1] = pa.y - h1; dl[2] = pa.z - h2; dl[3] = pa.w - h3;
        }
        __syncthreads();

        int tn = t + gridDim.x;
        pa = make_float4(0.f,0.f,0.f,0.f);
        if (tn < ntiles) {
            int row = tn * 16 + srr;
            if (row < n) pa = ((const float4*)g_agg)[(size_t)row * 16 + sc4];
        }

        float acc[2][4] = {{0.f,0.f,0.f,0.f},{0.f,0.f,0.f,0.f}};
#pragma unroll
        for (int ks = 0; ks < 8; ks++) {
            int kc = ks * 8 + tt;
            float ah0 = Zh[buf][g][kc],     ah1 = Zh[buf][g + 8][kc];
            float ah2 = Zh[buf][g][kc + 4], ah3 = Zh[buf][g + 8][kc + 4];
            float al0 = Zl[buf][g][kc],     al1 = Zl[buf][g + 8][kc];
            float al2 = Zl[buf][g][kc + 4], al3 = Zl[buf][g + 8][kc + 4];
#pragma unroll
            for (int t2 = 0; t2 < 2; t2++) {
                mma8f(acc[t2], ah0, ah1, ah2, ah3, wh[ks][t2][0], wh[ks][t2][1]);
                mma8f(acc[t2], ah0, ah1, ah2, ah3, wl[ks][t2][0], wl[ks][t2][1]);
                mma8f(acc[t2], al0, al1, al2, al3, wh[ks][t2][0], wh[ks][t2][1]);
            }
        }

        int r0 = t * 16;
        int rA = r0 + g, rB = r0 + g + 8;
#pragma unroll
        for (int t2 = 0; t2 < 2; t2++) {
            int col = nt0 + t2 * 8 + tt * 2;
            float e0 = acc[t2][0] + bias[t2].x, o0 = acc[t2][1] + bias[t2].y;
            float e1 = acc[t2][2] + bias[t2].x, o1 = acc[t2][3] + bias[t2].y;
            if (rA < n) {
                *(float2*)(g_y1 + (size_t)rA * 128 + col) = make_float2(e0, o0);
                sA[t2][0] += e0; qA[t2][0] += e0 * e0;
                sA[t2][1] += o0; qA[t2][1] += o0 * o0;
            }
            if (rB < n) {
                *(float2*)(g_y1 + (size_t)rB * 128 + col) = make_float2(e1, o1);
                sA[t2][0] += e1; qA[t2][0] += e1 * e1;
                sA[t2][1] += o1; qA[t2][1] += o1 * o1;
            }
        }
        buf ^= 1;
    }

#pragma unroll
    for (int t2 = 0; t2 < 2; t2++)
#pragma unroll
        for (int j = 0; j < 2; j++) {
#pragma unroll
            for (int off = 4; off < 32; off <<= 1) {
                sA[t2][j] += __shfl_xor_sync(0xffffffffu, sA[t2][j], off);
                qA[t2][j] += __shfl_xor_sync(0xffffffffu, qA[t2][j], off);
            }
        }
    if (g == 0) {
#pragma unroll
        for (int t2 = 0; t2 < 2; t2++) {
            int col = nt0 + t2 * 8 + tt * 2;
            atomicAdd(&g_stats[col], sA[t2][0]);
            atomicAdd(&g_stats[col + 1], sA[t2][1]);
            atomicAdd(&g_stats[128 + col], qA[t2][0]);
            atomicAdd(&g_stats[128 + col + 1], qA[t2][1]);
        }
    }
}

// ---------------------------------------------------------------------------
// GEMM2 (tensor, B-stationary): t = relu(bn1(y1)) -> y2 = t@W2 + b2 -> g_agg.
// BN1 computed per block from g_stats. BN2 stats fused.
// ---------------------------------------------------------------------------
__global__ __launch_bounds__(256, 2) void gemm2_tc_kernel(
    const float* __restrict__ W2, const float* __restrict__ b2,
    const float* __restrict__ bn1_g, const float* __restrict__ bn1_b,
    float nInv, int n, int ntiles)
{
    __shared__ float Zh[2][16][132];
    __shared__ float Zl[2][16][132];
    __shared__ __align__(16) float bsc[128];
    __shared__ __align__(16) float bsh[128];

    int tid = threadIdx.x;
    int wid = tid >> 5;
    int lane = tid & 31;
    int g = lane >> 2, tt = lane & 3;
    int nt0 = wid * 8;

    if (tid < 128) {
        float mean = g_stats[tid] * nInv;
        float var = fmaxf(g_stats[128 + tid] * nInv - mean * mean, 0.f);
        float inv = rsqrtf(var + 1e-5f);
        float sc = __ldg(&bn1_g[tid]) * inv;
        bsc[tid] = sc;
        bsh[tid] = __ldg(&bn1_b[tid]) - mean * sc;
    }

    float wh[16][2], wl[16][2];
#pragma unroll
    for (int ks = 0; ks < 16; ks++) {
        int col = nt0 + g;
        int k0 = ks * 8 + tt;
        float w0 = __ldg(&W2[k0 * 64 + col]);
        float w1 = __ldg(&W2[(k0 + 4) * 64 + col]);
        wh[ks][0] = tf32_hi(w0); wl[ks][0] = w0 - wh[ks][0];
        wh[ks][1] = tf32_hi(w1); wl[ks][1] = w1 - wh[ks][1];
    }
    float2 bias = *(const float2*)(b2 + nt0 + tt * 2);

    int srr = tid >> 4, sc4b = (tid & 15) * 2;

    float sA[2] = {0.f, 0.f}, qA[2] = {0.f, 0.f};
    __syncthreads();

    float4 p0 = make_float4(0.f,0.f,0.f,0.f), p1 = p0;
    int t = blockIdx.x;
    if (t < ntiles) {
        int row = t * 16 + srr;
        if (row < n) {
            p0 = ((const float4*)g_y1)[(size_t)row * 32 + sc4b];
            p1 = ((const float4*)g_y1)[(size_t)row * 32 + sc4b + 1];
        }
    }
    int buf = 0;
    for (; t < ntiles; t += gridDim.x) {
        {
#pragma unroll
            for (int j = 0; j < 2; j++) {
                float4 y = j ? p1 : p0;
                int c4 = sc4b + j;
                float4 sc = ((const float4*)bsc)[c4];
                float4 sh = ((const float4*)bsh)[c4];
                float z0 = fmaxf(fmaf(y.x, sc.x, sh.x), 0.f);
                float z1 = fmaxf(fmaf(y.y, sc.y, sh.y), 0.f);
                float z2 = fmaxf(fmaf(y.z, sc.z, sh.z), 0.f);
                float z3 = fmaxf(fmaf(y.w, sc.w, sh.w), 0.f);
                float* dh = &Zh[buf][srr][c4 * 4];
                float* dl = &Zl[buf][srr][c4 * 4];
                float h0 = tf32_hi(z0), h1 = tf32_hi(z1), h2 = tf32_hi(z2), h3 = tf32_hi(z3);
                dh[0] = h0; dh[1] = h1; dh[2] = h2; dh[3] = h3;
                dl[0] = z0 - h0; dl[1] = z1 - h1; dl[2] = z2 - h2; dl[3] = z3 - h3;
            }
        }
        __syncthreads();

        int tn = t + gridDim.x;
        p0 = make_float4(0.f,0.f,0.f,0.f); p1 = p0;
        if (tn < ntiles) {
            int row = tn * 16 + srr;
            if (row < n) {
                p0 = ((const float4*)g_y1)[(size_t)row * 32 + sc4b];
                p1 = ((const float4*)g_y1)[(size_t)row * 32 + sc4b + 1];
            }
        }

        float acc[4] = {0.f, 0.f, 0.f, 0.f};
#pragma unroll
        for (int ks = 0; ks < 16; ks++) {
            int kc = ks * 8 + tt;
            float ah0 = Zh[buf][g][kc],     ah1 = Zh[buf][g + 8][kc];
            float ah2 = Zh[buf][g][kc + 4], ah3 = Zh[buf][g + 8][kc + 4];
            float al0 = Zl[buf][g][kc],     al1 = Zl[buf][g + 8][kc];
            float al2 = Zl[buf][g][kc + 4], al3 = Zl[buf][g + 8][kc + 4];
            mma8f(acc, ah0, ah1, ah2, ah3, wh[ks][0], wh[ks][1]);
            mma8f(acc, ah0, ah1, ah2, ah3, wl[ks][0], wl[ks][1]);
            mma8f(acc, al0, al1, al2, al3, wh[ks][0], wh[ks][1]);
        }

        int r0 = t * 16;
        int rA = r0 + g, rB = r0 + g + 8;
        int col = nt0 + tt * 2;
        float e0 = acc[0] + bias.x, o0 = acc[1] + bias.y;
        float e1 = acc[2] + bias.x, o1 = acc[3] + bias.y;
        if (rA < n) {
            *(float2*)(g_agg + (size_t)rA * 64 + col) = make_float2(e0, o0);
            sA[0] += e0; qA[0] += e0 * e0;
            sA[1] += o0; qA[1] += o0 * o0;
        }
        if (rB < n) {
            *(float2*)(g_agg + (size_t)rB * 64 + col) = make_float2(e1, o1);
            sA[0] += e1; qA[0] += e1 * e1;
            sA[1] += o1; qA[1] += o1 * o1;
        }
        buf ^= 1;
    }

#pragma unroll
    for (int j = 0; j < 2; j++) {
#pragma unroll
        for (int off = 4; off < 32; off <<= 1) {
            sA[j] += __shfl_xor_sync(0xffffffffu, sA[j], off);
            qA[j] += __shfl_xor_sync(0xffffffffu, qA[j], off);
        }
    }
    if (g == 0) {
        int col = nt0 + tt * 2;
        atomicAdd(&g_stats[256 + col], sA[0]);
        atomicAdd(&g_stats[256 + col + 1], sA[1]);
        atomicAdd(&g_stats[320 + col], qA[0]);
        atomicAdd(&g_stats[320 + col + 1], qA[1]);
    }
}

// ---------------------------------------------------------------------------
// BN2 apply. mode 0: relu -> g_h. mode 1: -> nodeout + fused pooling.
// ---------------------------------------------------------------------------
__global__ __launch_bounds__(256) void bn2_apply_kernel(
    const float* __restrict__ bn2_g, const float* __restrict__ bn2_b,
    float* __restrict__ nodeout, const int* __restrict__ batch,
    float* __restrict__ gout, float nInv, int n, int mode)
{
    __shared__ __align__(16) float bsc[64];
    __shared__ __align__(16) float bsh[64];
    if (threadIdx.x < 64) {
        int t = threadIdx.x;
        float mean = g_stats[256 + t] * nInv;
        float var = fmaxf(g_stats[320 + t] * nInv - mean * mean, 0.f);
        float inv = rsqrtf(var + 1e-5f);
        float sc = __ldg(&bn2_g[t]) * inv;
        bsc[t] = sc;
        bsh[t] = __ldg(&bn2_b[t]) - mean * sc;
    }
    __syncthreads();

    int i = blockIdx.x * 256 + threadIdx.x;
    if (i >= n * 16) return;
    int c = i & 15;
    float4 y = ((const float4*)g_agg)[i];
    float4 sc = ((const float4*)bsc)[c];
    float4 sh = ((const float4*)bsh)[c];
    float4 v;
    v.x = fmaf(y.x, sc.x, sh.x);
    v.y = fmaf(y.y, sc.y, sh.y);
    v.z = fmaf(y.z, sc.z, sh.z);
    v.w = fmaf(y.w, sc.w, sh.w);
    if (mode == 0) {
        v.x = fmaxf(v.x, 0.f); v.y = fmaxf(v.y, 0.f);
        v.z = fmaxf(v.z, 0.f); v.w = fmaxf(v.w, 0.f);
        ((float4*)g_h)[i] = v;
    } else {
        ((float4*)nodeout)[i] = v;
        int nid = i >> 4;
        int b = __ldg(&batch[nid]);
        red_add_v4(gout + (size_t)b * 64 + c * 4, v);
        if (c == 0) atomicAdd(&g_cnt[b], 1.0f);
    }
}

__global__ __launch_bounds__(256) void divide_kernel(float* __restrict__ gout, int b)
{
    int i = blockIdx.x * 256 + threadIdx.x;
    if (i < b * 64) gout[i] = gout[i] / (g_cnt[i >> 6] + 1e-9f);
}

// ---------------------------------------------------------------------------
// Launch
// ---------------------------------------------------------------------------
extern "C" void kernel_launch(void* const* d_in, const int* in_sizes, int n_in,
                              void* d_out, int out_size)
{
    const float* atom_emb = (const float*)d_in[0];
    const float* bond_emb = (const float*)d_in[1];
    const float* eps      = (const float*)d_in[2];
    const float* W1       = (const float*)d_in[3];
    const float* b1       = (const float*)d_in[4];
    const float* bn1_g    = (const float*)d_in[5];
    const float* bn1_b    = (const float*)d_in[6];
    const float* W2       = (const float*)d_in[7];
    const float* b2       = (const float*)d_in[8];
    const float* bn2_g    = (const float*)d_in[9];
    const float* bn2_b    = (const float*)d_in[10];
    const int* x_feat     = (const int*)d_in[11];
    const int* edge_index = (const int*)d_in[12];
    const int* edge_attr  = (const int*)d_in[13];
    const int* batch      = (const int*)d_in[14];

    int n = in_sizes[11] / 9;
    int e = in_sizes[12] / 2;
    int b = out_size / 64 - n;
    float* nodeout = (float*)d_out;
    float* gout = nodeout + (size_t)n * 64;

    int nodeGrid = (n * 16 + 255) / 256;
    int edgeBlocks = (e + 255) / 256;
    int scanBlocks = (n + 1023) / 1024;
    int ntiles = (n + 15) / 16;
    int gemmGrid = 296;   // 2 blocks/SM x 148 SMs
    int edgeGrid = 1036;
    float nInv = 1.0f / (float)n;

    atom_kernel<<<nodeGrid, 256>>>(atom_emb, x_feat, n);

    // CSR build (one-time per call)
    clear_off_kernel<<<(n + 256) / 256, 256>>>(n);
    hist_kernel<<<edgeBlocks, 256>>>(edge_index, e);
    scan_partial_kernel<<<scanBlocks, 1024>>>(n);
    scan_bsums_kernel<<<1, 32>>>(scanBlocks);
    scan_final_kernel<<<scanBlocks, 1024>>>(n);
    copy_cur_kernel<<<(n + 255) / 256, 256>>>(n);
    scatter_kernel<<<edgeBlocks, 256>>>(edge_index, edge_attr, e);

    clear_pool_kernel<<<(b * 64 + 255) / 256, 256>>>(gout, b);

    for (int l = 0; l < 4; l++) {
        edge_csr_kernel<<<edgeGrid, 256>>>(bond_emb + l * 1536, eps + l, n);
        gemm1_tc_kernel<<<gemmGrid, 256>>>(W1 + l * 64 * 128, b1 + l * 128, n, ntiles);
        gemm2_tc_kernel<<<gemmGrid, 256>>>(W2 + l * 128 * 64, b2 + l * 64,
                                           bn1_g + l * 128, bn1_b + l * 128, nInv, n, ntiles);
        bn2_apply_kernel<<<nodeGrid, 256>>>(bn2_g + l * 64, bn2_b + l * 64,
                                            nodeout, batch, gout, nInv, n, (l == 3) ? 1 : 0);
    }

    divide_kernel<<<(b * 64 + 255) / 256, 256>>>(gout, b);
}